// round 8
// baseline (speedup 1.0000x reference)
#include <cuda_runtime.h>
#include <cstdint>

// Fixed shapes
#define BB    16
#define RS    128
#define TT    128
#define HH    32
#define GG    96
#define NV    258
#define NTOK  (BB*RS*TT)     // 262144
#define RPAD  36             // padded row length (floats) for weight rows
#define MSIZE (GG*RPAD)      // 3456 floats per matrix

typedef unsigned long long u64;

// -------- device scratch --------
__device__ float g_embW[NV*GG];           // W_ih0[:, :64] @ embed^T -> [258][96]
__device__ float g_Wp[6*MSIZE];           // 0:M 1:Wh0 2:Wi1 3:Wh1 4:Wi2 5:Wh2  ([96][36] rows)
__device__ float g_base[GG];              // b_ih0 + Wih0 @ b_h2e
__device__ float g_w64[GG];               // Wih0[:,64]
__device__ float g_h[(size_t)NTOK*HH];    // top-layer outputs [B][R][T][H]
__device__ int   g_flag[RS*4];            // per (row, warp) progress

// -------- helpers --------
__device__ __forceinline__ float sigf(float x)   { return __fdividef(1.0f, 1.0f + __expf(-x)); }
__device__ __forceinline__ float tanh_f(float x) { return __fdividef(2.0f, 1.0f + __expf(-2.0f*x)) - 1.0f; }

__device__ __forceinline__ void st_release(int* p, int v) {
    asm volatile("st.release.gpu.global.s32 [%0], %1;" :: "l"(p), "r"(v) : "memory");
}
__device__ __forceinline__ int ld_acquire(const int* p) {
    int v;
    asm volatile("ld.acquire.gpu.global.s32 %0, [%1];" : "=r"(v) : "l"(p) : "memory");
    return v;
}

// f32x2 packed ops
#define FMA2(d,a,b) asm("fma.rn.f32x2 %0, %1, %2, %0;" : "+l"(d) : "l"(a), "l"(b))
#define ADD2(d,b)   asm("add.rn.f32x2 %0, %0, %1;"     : "+l"(d) : "l"(b))
#define PACK2(o,lo,hi) asm("mov.b64 %0, {%1, %2};" : "=l"(o) : "r"(__float_as_uint(lo)), "r"(__float_as_uint(hi)))
#define UNPK2(lo,hi,in) { unsigned _l,_h; asm("mov.b64 {%0, %1}, %2;" : "=r"(_l), "=r"(_h) : "l"(in)); lo=__uint_as_float(_l); hi=__uint_as_float(_h); }

// -------- kernel 0: zero flags --------
__global__ void zero_flag_kernel() {
    int i = blockIdx.x*blockDim.x + threadIdx.x;
    if (i < RS*4) g_flag[i] = 0;
}

// -------- kernel 1: precompute folded weights --------
__global__ void precompute_kernel(
    const float* __restrict__ emb,   // [258][64]
    const float* __restrict__ wih0,  // [96][65]
    const float* __restrict__ bih0,  // [96]
    const float* __restrict__ wh2e,  // [65][32]
    const float* __restrict__ bh2e,  // [65]
    const float* __restrict__ whh0,  // [96][32]
    const float* __restrict__ wih1,  // [96][32]
    const float* __restrict__ whh1,
    const float* __restrict__ wih2,
    const float* __restrict__ whh2)
{
    int g = threadIdx.x;     // 0..95
    int blk = blockIdx.x;
    if (blk < NV) {
        float s = 0.f;
        #pragma unroll
        for (int e = 0; e < 64; ++e) s = fmaf(wih0[g*65+e], emb[blk*64+e], s);
        g_embW[blk*GG + g] = s;
    } else if (blk == NV) {
        for (int k = 0; k < HH; ++k) {
            float s = 0.f;
            for (int i = 0; i < 65; ++i) s = fmaf(wih0[g*65+i], wh2e[i*HH+k], s);
            g_Wp[g*RPAD + k] = s;            // M = Wih0[:, :65] @ Wh2e
        }
        float s = 0.f;
        for (int i = 0; i < 65; ++i) s = fmaf(wih0[g*65+i], bh2e[i], s);
        g_base[g] = bih0[g] + s;
        g_w64[g]  = wih0[g*65 + 64];
    } else {
        int m = blk - NV - 1;   // 0..4 -> Wh0, Wi1, Wh1, Wi2, Wh2
        const float* w = (m==0)?whh0 : (m==1)?wih1 : (m==2)?whh1 : (m==3)?wih2 : whh2;
        for (int k = 0; k < HH; ++k)
            g_Wp[(1+m)*MSIZE + g*RPAD + k] = w[g*HH + k];
    }
}

// one matvec side: 3 gate rows x 32 k, 2 batch-pairs, f32x2.
// W: smem float base; S: u64* stage [64] (S[k]=pair01, S[32+k]=pair23)
#define SIDE(W, S, AR0,AR1,AZ0,AZ1,AN0,AN1) { \
  _Pragma("unroll") \
  for (int kq = 0; kq < 8; ++kq) { \
    float4 wr = *(const float4*)((W)+rowR+kq*4); \
    float4 wz = *(const float4*)((W)+rowZ+kq*4); \
    float4 wn = *(const float4*)((W)+rowN+kq*4); \
    ulonglong2 pa = *(const ulonglong2*)((S)+4*kq); \
    ulonglong2 pb = *(const ulonglong2*)((S)+4*kq+2); \
    ulonglong2 qa = *(const ulonglong2*)((S)+32+4*kq); \
    ulonglong2 qb = *(const ulonglong2*)((S)+32+4*kq+2); \
    u64 wp; \
    PACK2(wp, wr.x, wr.x); FMA2(AR0,wp,pa.x); FMA2(AR1,wp,qa.x); \
    PACK2(wp, wz.x, wz.x); FMA2(AZ0,wp,pa.x); FMA2(AZ1,wp,qa.x); \
    PACK2(wp, wn.x, wn.x); FMA2(AN0,wp,pa.x); FMA2(AN1,wp,qa.x); \
    PACK2(wp, wr.y, wr.y); FMA2(AR0,wp,pa.y); FMA2(AR1,wp,qa.y); \
    PACK2(wp, wz.y, wz.y); FMA2(AZ0,wp,pa.y); FMA2(AZ1,wp,qa.y); \
    PACK2(wp, wn.y, wn.y); FMA2(AN0,wp,pa.y); FMA2(AN1,wp,qa.y); \
    PACK2(wp, wr.z, wr.z); FMA2(AR0,wp,pb.x); FMA2(AR1,wp,qb.x); \
    PACK2(wp, wz.z, wz.z); FMA2(AZ0,wp,pb.x); FMA2(AZ1,wp,qb.x); \
    PACK2(wp, wn.z, wn.z); FMA2(AN0,wp,pb.x); FMA2(AN1,wp,qb.x); \
    PACK2(wp, wr.w, wr.w); FMA2(AR0,wp,pb.y); FMA2(AR1,wp,qb.y); \
    PACK2(wp, wz.w, wz.w); FMA2(AZ0,wp,pb.y); FMA2(AZ1,wp,qb.y); \
    PACK2(wp, wn.w, wn.w); FMA2(AN0,wp,pb.y); FMA2(AN1,wp,qb.y); \
  } }

#define GRUUP(h, aR, aZ, aNi, aNh) { \
    float rg = sigf(aR); float zg = sigf(aZ); \
    float ng = tanh_f(aNi + rg*(aNh)); \
    h = fmaf(zg, (h) - ng, ng); }

// unpack 8 accums -> 4 GRU updates -> pack into stage
#define GRU4(H0,H1,H2,H3, SDST) { \
    float r0,r1,r2,r3, z0,z1,z2,z3, n0,n1,n2,n3, m0,m1,m2,m3; \
    UNPK2(r0,r1,aR0); UNPK2(r2,r3,aR1); \
    UNPK2(z0,z1,aZ0); UNPK2(z2,z3,aZ1); \
    UNPK2(n0,n1,aN0); UNPK2(n2,n3,aN1); \
    UNPK2(m0,m1,aM0); UNPK2(m2,m3,aM1); \
    GRUUP(H0, r0, z0, n0, m0) \
    GRUUP(H1, r1, z1, n1, m1) \
    GRUUP(H2, r2, z2, n2, m2) \
    GRUUP(H3, r3, z3, n3, m3) \
    __syncwarp(); \
    { u64 v; PACK2(v, H0, H1); (SDST)[j] = v; PACK2(v, H2, H3); (SDST)[32+j] = v; } \
    __syncwarp(); }

// -------- kernel 2: wavefront GRU --------
// grid = 128 CTAs (one per row), 128 threads = 4 warps, warp w owns batches 4w..4w+3.
__global__ void __launch_bounds__(128, 1) wave_kernel(
    const int*   __restrict__ x,
    const float* __restrict__ bhh0, const float* __restrict__ bih1,
    const float* __restrict__ bhh1, const float* __restrict__ bih2,
    const float* __restrict__ bhh2)
{
    extern __shared__ float sm[];
    float* sW   = sm;                              // 6*MSIZE floats (82944 B)
    u64*   stg  = (u64*)(sm + 6*MSIZE);            // 4 warps * 4 stages * 64 u64 (8192 B)
    int*   stok = (int*)(sm + 6*MSIZE + 2048);     // 16*128 tokens (8192 B)

    const int tid = threadIdx.x;
    const int r   = blockIdx.x;
    const int w   = tid >> 5;
    const int j   = tid & 31;

    {   // stage weights, zero stages, stage tokens
        const float4* src = (const float4*)g_Wp;
        float4* dst = (float4*)sW;
        for (int i = tid; i < 6*MSIZE/4; i += 128) dst[i] = src[i];
        for (int i = tid; i < 1024; i += 128) stg[i] = 0ull;
        for (int i = tid; i < BB*TT; i += 128) {
            int b = i >> 7, tt = i & 127;
            stok[i] = x[(b*RS + r)*TT + tt];
        }
    }
    __syncthreads();

    const int rowR = j*RPAD, rowZ = (32+j)*RPAD, rowN = (64+j)*RPAD;
    const float* W_M  = sW;
    const float* W_h0 = sW + 1*MSIZE;
    const float* W_i1 = sW + 2*MSIZE;
    const float* W_h1 = sW + 3*MSIZE;
    const float* W_i2 = sW + 4*MSIZE;
    const float* W_h2 = sW + 5*MSIZE;

    u64* S_pv = stg + w*256;
    u64* S_h0 = S_pv + 64;
    u64* S_h1 = S_pv + 128;
    u64* S_h2 = S_pv + 192;

    const float rowpos = (float)r * (1.0f/64.0f) - 1.0f;
    const float k0r  = g_base[j]    + g_w64[j]   *rowpos + bhh0[j];
    const float k0z  = g_base[32+j] + g_w64[32+j]*rowpos + bhh0[32+j];
    const float k0n  = g_base[64+j] + g_w64[64+j]*rowpos;
    const float k0m  = bhh0[64+j];
    const float k1r  = bih1[j] + bhh1[j];
    const float k1z  = bih1[32+j] + bhh1[32+j];
    const float k1n  = bih1[64+j];
    const float k1m  = bhh1[64+j];
    const float k2r  = bih2[j] + bhh2[j];
    const float k2z  = bih2[32+j] + bhh2[32+j];
    const float k2n  = bih2[64+j];
    const float k2m  = bhh2[64+j];
    u64 cK0r,cK0z,cK0n,cK0m, cK1r,cK1z,cK1n,cK1m, cK2r,cK2z,cK2n,cK2m;
    PACK2(cK0r,k0r,k0r); PACK2(cK0z,k0z,k0z); PACK2(cK0n,k0n,k0n); PACK2(cK0m,k0m,k0m);
    PACK2(cK1r,k1r,k1r); PACK2(cK1z,k1z,k1z); PACK2(cK1n,k1n,k1n); PACK2(cK1m,k1m,k1m);
    PACK2(cK2r,k2r,k2r); PACK2(cK2z,k2z,k2z); PACK2(cK2n,k2n,k2n); PACK2(cK2m,k2m,k2m);

    const int b0 = w*4;
    float* out0 = g_h + (size_t)((b0+0)*RS + r)*TT*HH;
    float* out1 = g_h + (size_t)((b0+1)*RS + r)*TT*HH;
    float* out2 = g_h + (size_t)((b0+2)*RS + r)*TT*HH;
    float* out3 = g_h + (size_t)((b0+3)*RS + r)*TT*HH;
    const int rp = (r > 0) ? (r-1) : 0;
    const float* pr0 = g_h + (size_t)((b0+0)*RS + rp)*TT*HH;
    const float* pr1 = g_h + (size_t)((b0+1)*RS + rp)*TT*HH;
    const float* pr2 = g_h + (size_t)((b0+2)*RS + rp)*TT*HH;
    const float* pr3 = g_h + (size_t)((b0+3)*RS + rp)*TT*HH;
    int*       pub = &g_flag[r*4 + w];
    const int* pf  = &g_flag[rp*4 + w];

    float h0_0=0.f,h0_1=0.f,h0_2=0.f,h0_3=0.f;
    float h1_0=0.f,h1_1=0.f,h1_2=0.f,h1_3=0.f;
    float h2_0=0.f,h2_1=0.f,h2_2=0.f,h2_3=0.f;

    for (int t = 0; t < TT; ++t) {
        // issue embW loads early (consumed only after both layer-0 matvec sides)
        const int tk0 = stok[(b0+0)*TT + t];
        const int tk1 = stok[(b0+1)*TT + t];
        const int tk2 = stok[(b0+2)*TT + t];
        const int tk3 = stok[(b0+3)*TT + t];
        const float* e0 = g_embW + tk0*GG;
        const float* e1 = g_embW + tk1*GG;
        const float* e2 = g_embW + tk2*GG;
        const float* e3 = g_embW + tk3*GG;
        float er0 = __ldg(e0+j),    er1 = __ldg(e1+j),    er2 = __ldg(e2+j),    er3 = __ldg(e3+j);
        float ez0 = __ldg(e0+32+j), ez1 = __ldg(e1+32+j), ez2 = __ldg(e2+32+j), ez3 = __ldg(e3+32+j);
        float en0 = __ldg(e0+64+j), en1 = __ldg(e1+64+j), en2 = __ldg(e2+64+j), en3 = __ldg(e3+64+j);

        float p0=0.f, p1=0.f, p2=0.f, p3=0.f;
        if (r > 0) {
            while (ld_acquire(pf) <= t) { }
            p0 = __ldcg(pr0 + t*HH + j);
            p1 = __ldcg(pr1 + t*HH + j);
            p2 = __ldcg(pr2 + t*HH + j);
            p3 = __ldcg(pr3 + t*HH + j);
        }

        // ---- layer 0: h-side first (hides pv/embW load latency) ----
        u64 aR0=cK0r, aR1=cK0r, aZ0=cK0z, aZ1=cK0z, aN0=cK0n, aN1=cK0n, aM0=cK0m, aM1=cK0m;
        SIDE(W_h0, S_h0, aR0,aR1,aZ0,aZ1,aM0,aM1)
        if (r > 0) {
            __syncwarp();
            { u64 v; PACK2(v, p0, p1); S_pv[j] = v; PACK2(v, p2, p3); S_pv[32+j] = v; }
            __syncwarp();
            SIDE(W_M, S_pv, aR0,aR1,aZ0,aZ1,aN0,aN1)
        }
        // fold in embW (loads returned by now)
        {
            u64 tv;
            PACK2(tv, er0, er1); ADD2(aR0, tv); PACK2(tv, er2, er3); ADD2(aR1, tv);
            PACK2(tv, ez0, ez1); ADD2(aZ0, tv); PACK2(tv, ez2, ez3); ADD2(aZ1, tv);
            PACK2(tv, en0, en1); ADD2(aN0, tv); PACK2(tv, en2, en3); ADD2(aN1, tv);
        }
        GRU4(h0_0,h0_1,h0_2,h0_3, S_h0)

        // ---- layer 1 ----
        aR0=cK1r; aR1=cK1r; aZ0=cK1z; aZ1=cK1z; aN0=cK1n; aN1=cK1n; aM0=cK1m; aM1=cK1m;
        SIDE(W_i1, S_h0, aR0,aR1,aZ0,aZ1,aN0,aN1)
        SIDE(W_h1, S_h1, aR0,aR1,aZ0,aZ1,aM0,aM1)
        GRU4(h1_0,h1_1,h1_2,h1_3, S_h1)

        // ---- layer 2 ----
        aR0=cK2r; aR1=cK2r; aZ0=cK2z; aZ1=cK2z; aN0=cK2n; aN1=cK2n; aM0=cK2m; aM1=cK2m;
        SIDE(W_i2, S_h1, aR0,aR1,aZ0,aZ1,aN0,aN1)
        SIDE(W_h2, S_h2, aR0,aR1,aZ0,aZ1,aM0,aM1)
        GRU4(h2_0,h2_1,h2_2,h2_3, S_h2)

        // publish top-layer output + flag (release)
        __stcg(out0 + t*HH + j, h2_0);
        __stcg(out1 + t*HH + j, h2_1);
        __stcg(out2 + t*HH + j, h2_2);
        __stcg(out3 + t*HH + j, h2_3);
        __syncwarp();
        if (j == 0) st_release(pub, t + 1);
    }
}

// -------- kernel 3: output projection (8 tokens per warp, f32x2 over token pairs) --------
__global__ void __launch_bounds__(256) proj_kernel(
    const float* __restrict__ wout,   // [258][32]
    const float* __restrict__ bout,   // [258]
    float* __restrict__ pred)         // [262144][258]
{
    __shared__ float ws[32][264];
    __shared__ float bs[288];
    int tid = threadIdx.x;
    for (int i = tid; i < NV*HH; i += 256) {
        int v = i >> 5, h = i & 31;
        ws[h][v] = wout[i];
    }
    for (int i = tid; i < NV; i += 256) bs[i] = bout[i];
    __syncthreads();

    int warp = tid >> 5, lane = tid & 31;
    int tok0 = (blockIdx.x*8 + warp) * 8;

    float hv[8];
    #pragma unroll
    for (int i = 0; i < 8; ++i) hv[i] = g_h[(size_t)(tok0+i)*HH + lane];

    u64 acc[4][9];
    #pragma unroll
    for (int k = 0; k < 9; ++k) {
        int v = lane + 32*k;
        float b = (v < NV) ? bs[v] : 0.f;
        #pragma unroll
        for (int p = 0; p < 4; ++p) PACK2(acc[p][k], b, b);
    }
    #pragma unroll 4
    for (int h = 0; h < 32; ++h) {
        u64 w2[9];
        #pragma unroll
        for (int k = 0; k < 9; ++k) {
            int v = lane + 32*k;
            float wv = (v < NV) ? ws[h][v] : 0.f;
            PACK2(w2[k], wv, wv);
        }
        #pragma unroll
        for (int p = 0; p < 4; ++p) {
            float hb0 = __shfl_sync(0xffffffffu, hv[2*p],   h);
            float hb1 = __shfl_sync(0xffffffffu, hv[2*p+1], h);
            u64 hp; PACK2(hp, hb0, hb1);
            #pragma unroll
            for (int k = 0; k < 9; ++k) FMA2(acc[p][k], w2[k], hp);
        }
    }
    #pragma unroll
    for (int p = 0; p < 4; ++p) {
        size_t ba = (size_t)(tok0+2*p)*NV;
        size_t bb = (size_t)(tok0+2*p+1)*NV;
        #pragma unroll
        for (int k = 0; k < 9; ++k) {
            int v = lane + 32*k;
            float lo, hi; UNPK2(lo, hi, acc[p][k]);
            if (v < NV) { pred[ba + v] = lo; pred[bb + v] = hi; }
        }
    }
}

// -------- launch --------
extern "C" void kernel_launch(void* const* d_in, const int* in_sizes, int n_in,
                              void* d_out, int out_size)
{
    const int*   x    = (const int*)  d_in[0];
    const float* emb  = (const float*)d_in[1];
    const float* wih0 = (const float*)d_in[2];
    const float* whh0 = (const float*)d_in[3];
    const float* bih0 = (const float*)d_in[4];
    const float* bhh0 = (const float*)d_in[5];
    const float* wih1 = (const float*)d_in[6];
    const float* whh1 = (const float*)d_in[7];
    const float* bih1 = (const float*)d_in[8];
    const float* bhh1 = (const float*)d_in[9];
    const float* wih2 = (const float*)d_in[10];
    const float* whh2 = (const float*)d_in[11];
    const float* bih2 = (const float*)d_in[12];
    const float* bhh2 = (const float*)d_in[13];
    const float* wh2e = (const float*)d_in[14];
    const float* bh2e = (const float*)d_in[15];
    const float* wout = (const float*)d_in[16];
    const float* bout = (const float*)d_in[17];
    float* pred = (float*)d_out;

    // actual use: 82944 (weights) + 8192 (stages) + 8192 (tokens) = 99328 B.
    // Request 118784 B so only one CTA fits per SM (keeps all 128 rows on 128 distinct SMs).
    const int smem_bytes = 118784;
    cudaFuncSetAttribute(wave_kernel, cudaFuncAttributeMaxDynamicSharedMemorySize, smem_bytes);

    zero_flag_kernel<<<2, 256>>>();
    precompute_kernel<<<NV + 6, GG>>>(emb, wih0, bih0, wh2e, bh2e,
                                      whh0, wih1, whh1, wih2, whh2);
    wave_kernel<<<RS, 128, smem_bytes>>>(x, bhh0, bih1, bhh1, bih2, bhh2);
    proj_kernel<<<NTOK/64, 256>>>(wout, bout, pred);
}

// round 9
// speedup vs baseline: 1.5148x; 1.5148x over previous
#include <cuda_runtime.h>
#include <cstdint>

// Fixed shapes
#define BB    16
#define RS    128
#define TT    128
#define HH    32
#define GG    96
#define NV    258
#define NTOK  (BB*RS*TT)     // 262144
#define RPAD  36             // padded row length (floats) for weight rows
#define MSIZE (GG*RPAD)      // 3456 floats per matrix

// -------- device scratch --------
__device__ float g_embW[NV*GG];           // W_ih0[:, :64] @ embed^T -> [258][96]
__device__ float g_Wp[6*MSIZE];           // 0:M 1:Wh0 2:Wi1 3:Wh1 4:Wi2 5:Wh2  ([96][36] rows)
__device__ float g_base[GG];              // b_ih0 + Wih0 @ b_h2e
__device__ float g_w64[GG];               // Wih0[:,64]
__device__ float g_h[(size_t)NTOK*HH];    // top-layer outputs [B][R][T][H]
__device__ int   g_flag[RS*4];            // per (row, warp) progress

// -------- helpers --------
__device__ __forceinline__ float sigf(float x)   { return __fdividef(1.0f, 1.0f + __expf(-x)); }
__device__ __forceinline__ float tanh_f(float x) { return __fdividef(2.0f, 1.0f + __expf(-2.0f*x)) - 1.0f; }

__device__ __forceinline__ void st_release(int* p, int v) {
    asm volatile("st.release.gpu.global.s32 [%0], %1;" :: "l"(p), "r"(v) : "memory");
}
__device__ __forceinline__ int ld_acquire(const int* p) {
    int v;
    asm volatile("ld.acquire.gpu.global.s32 %0, [%1];" : "=r"(v) : "l"(p) : "memory");
    return v;
}

// -------- kernel 0: zero flags --------
__global__ void zero_flag_kernel() {
    int i = blockIdx.x*blockDim.x + threadIdx.x;
    if (i < RS*4) g_flag[i] = 0;
}

// -------- kernel 1: precompute folded weights --------
__global__ void precompute_kernel(
    const float* __restrict__ emb,   // [258][64]
    const float* __restrict__ wih0,  // [96][65]
    const float* __restrict__ bih0,  // [96]
    const float* __restrict__ wh2e,  // [65][32]
    const float* __restrict__ bh2e,  // [65]
    const float* __restrict__ whh0,  // [96][32]
    const float* __restrict__ wih1,  // [96][32]
    const float* __restrict__ whh1,
    const float* __restrict__ wih2,
    const float* __restrict__ whh2)
{
    int g = threadIdx.x;     // 0..95
    int blk = blockIdx.x;
    if (blk < NV) {
        float s = 0.f;
        #pragma unroll
        for (int e = 0; e < 64; ++e) s = fmaf(wih0[g*65+e], emb[blk*64+e], s);
        g_embW[blk*GG + g] = s;
    } else if (blk == NV) {
        for (int k = 0; k < HH; ++k) {
            float s = 0.f;
            for (int i = 0; i < 65; ++i) s = fmaf(wih0[g*65+i], wh2e[i*HH+k], s);
            g_Wp[g*RPAD + k] = s;            // M = Wih0[:, :65] @ Wh2e
        }
        float s = 0.f;
        for (int i = 0; i < 65; ++i) s = fmaf(wih0[g*65+i], bh2e[i], s);
        g_base[g] = bih0[g] + s;
        g_w64[g]  = wih0[g*65 + 64];
    } else {
        int m = blk - NV - 1;   // 0..4 -> Wh0, Wi1, Wh1, Wi2, Wh2
        const float* w = (m==0)?whh0 : (m==1)?wih1 : (m==2)?whh1 : (m==3)?wih2 : whh2;
        for (int k = 0; k < HH; ++k)
            g_Wp[(1+m)*MSIZE + g*RPAD + k] = w[g*HH + k];
    }
}

// 12 FMAs: one k-slice, r/z into aR/aZ, n into named targets
#define FG(wr_,wz_,wn_, v0,v1,v2,v3, N0,N1,N2,N3) \
    aR0=fmaf(wr_,v0,aR0); aR1=fmaf(wr_,v1,aR1); aR2=fmaf(wr_,v2,aR2); aR3=fmaf(wr_,v3,aR3); \
    aZ0=fmaf(wz_,v0,aZ0); aZ1=fmaf(wz_,v1,aZ1); aZ2=fmaf(wz_,v2,aZ2); aZ3=fmaf(wz_,v3,aZ3); \
    N0 =fmaf(wn_,v0,N0);  N1 =fmaf(wn_,v1,N1);  N2 =fmaf(wn_,v2,N2);  N3 =fmaf(wn_,v3,N3);

// one matvec side: 3 gate rows x 32 k x 4 batches. W: smem float base;
// S: float2* stage [64] (S[k]=(b0,b1), S[32+k]=(b2,b3)). n-target selectable.
#define SIDE1(W, S, N0,N1,N2,N3) { \
    const float4* S4 = (const float4*)(S); \
    _Pragma("unroll") \
    for (int kq = 0; kq < 8; ++kq) { \
        float4 wr = *(const float4*)((W)+rowR+kq*4); \
        float4 wz = *(const float4*)((W)+rowZ+kq*4); \
        float4 wn = *(const float4*)((W)+rowN+kq*4); \
        float4 xa = S4[2*kq], xb = S4[2*kq+1], xc = S4[16+2*kq], xd = S4[16+2*kq+1]; \
        FG(wr.x,wz.x,wn.x, xa.x,xa.y,xc.x,xc.y, N0,N1,N2,N3) \
        FG(wr.y,wz.y,wn.y, xa.z,xa.w,xc.z,xc.w, N0,N1,N2,N3) \
        FG(wr.z,wz.z,wn.z, xb.x,xb.y,xd.x,xd.y, N0,N1,N2,N3) \
        FG(wr.w,wz.w,wn.w, xb.z,xb.w,xd.z,xd.w, N0,N1,N2,N3) \
    } }

#define GRUUP(h, aR, aZ, aNi, aNh) { \
    float rg = sigf(aR); float zg = sigf(aZ); \
    float ng = tanh_f(aNi + rg*(aNh)); \
    h = fmaf(zg, (h) - ng, ng); }

#define GRU4(H0,H1,H2,H3, SDST) { \
    GRUUP(H0, aR0, aZ0, aN0, aM0) \
    GRUUP(H1, aR1, aZ1, aN1, aM1) \
    GRUUP(H2, aR2, aZ2, aN2, aM2) \
    GRUUP(H3, aR3, aZ3, aN3, aM3) \
    __syncwarp(); \
    (SDST)[j]    = make_float2(H0, H1); \
    (SDST)[32+j] = make_float2(H2, H3); \
    __syncwarp(); }

// -------- kernel 2: wavefront GRU --------
// grid = 128 CTAs (one per row), 128 threads = 4 warps, warp w owns batches 4w..4w+3.
__global__ void __launch_bounds__(128, 1) wave_kernel(
    const int*   __restrict__ x,
    const float* __restrict__ bhh0, const float* __restrict__ bih1,
    const float* __restrict__ bhh1, const float* __restrict__ bih2,
    const float* __restrict__ bhh2)
{
    extern __shared__ float sm[];
    float*  sW   = sm;                              // 6*MSIZE floats (82944 B)
    float2* stg  = (float2*)(sm + 6*MSIZE);         // 4 warps * 4 stages * 64 float2 (8192 B)
    int*    stok = (int*)(sm + 6*MSIZE + 2048);     // 16*128 tokens (8192 B)

    const int tid = threadIdx.x;
    const int r   = blockIdx.x;
    const int w   = tid >> 5;
    const int j   = tid & 31;

    {   // stage weights, zero stages, stage tokens
        const float4* src = (const float4*)g_Wp;
        float4* dst = (float4*)sW;
        for (int i = tid; i < 6*MSIZE/4; i += 128) dst[i] = src[i];
        for (int i = tid; i < 1024; i += 128) stg[i] = make_float2(0.f, 0.f);
        for (int i = tid; i < BB*TT; i += 128) {
            int b = i >> 7, tt = i & 127;
            stok[i] = x[(b*RS + r)*TT + tt];
        }
    }
    __syncthreads();

    const int rowR = j*RPAD, rowZ = (32+j)*RPAD, rowN = (64+j)*RPAD;
    const float* W_M  = sW;
    const float* W_h0 = sW + 1*MSIZE;
    const float* W_i1 = sW + 2*MSIZE;
    const float* W_h1 = sW + 3*MSIZE;
    const float* W_i2 = sW + 4*MSIZE;
    const float* W_h2 = sW + 5*MSIZE;

    float2* S_pv = stg + w*256;
    float2* S_h0 = S_pv + 64;
    float2* S_h1 = S_pv + 128;
    float2* S_h2 = S_pv + 192;

    const float rowpos = (float)r * (1.0f/64.0f) - 1.0f;
    const float k0r  = g_base[j]    + g_w64[j]   *rowpos + bhh0[j];
    const float k0z  = g_base[32+j] + g_w64[32+j]*rowpos + bhh0[32+j];
    const float k0n  = g_base[64+j] + g_w64[64+j]*rowpos;
    const float k0m  = bhh0[64+j];
    const float k1r  = bih1[j] + bhh1[j];
    const float k1z  = bih1[32+j] + bhh1[32+j];
    const float k1n  = bih1[64+j];
    const float k1m  = bhh1[64+j];
    const float k2r  = bih2[j] + bhh2[j];
    const float k2z  = bih2[32+j] + bhh2[32+j];
    const float k2n  = bih2[64+j];
    const float k2m  = bhh2[64+j];

    const int b0 = w*4;
    float* out0 = g_h + (size_t)((b0+0)*RS + r)*TT*HH;
    float* out1 = g_h + (size_t)((b0+1)*RS + r)*TT*HH;
    float* out2 = g_h + (size_t)((b0+2)*RS + r)*TT*HH;
    float* out3 = g_h + (size_t)((b0+3)*RS + r)*TT*HH;
    const int rp = (r > 0) ? (r-1) : 0;
    const float* pr0 = g_h + (size_t)((b0+0)*RS + rp)*TT*HH;
    const float* pr1 = g_h + (size_t)((b0+1)*RS + rp)*TT*HH;
    const float* pr2 = g_h + (size_t)((b0+2)*RS + rp)*TT*HH;
    const float* pr3 = g_h + (size_t)((b0+3)*RS + rp)*TT*HH;
    int*       pub = &g_flag[r*4 + w];
    const int* pf  = &g_flag[rp*4 + w];

    float h0_0=0.f,h0_1=0.f,h0_2=0.f,h0_3=0.f;
    float h1_0=0.f,h1_1=0.f,h1_2=0.f,h1_3=0.f;
    float h2_0=0.f,h2_1=0.f,h2_2=0.f,h2_3=0.f;

    int flag_cache = 0;   // cached producer progress (acquire-loaded)

    for (int t = 0; t < TT; ++t) {
        // ---- issue embW loads early (consumed only after layer-0 h-side) ----
        const int tk0 = stok[(b0+0)*TT + t];
        const int tk1 = stok[(b0+1)*TT + t];
        const int tk2 = stok[(b0+2)*TT + t];
        const int tk3 = stok[(b0+3)*TT + t];
        const float* e0 = g_embW + tk0*GG;
        const float* e1 = g_embW + tk1*GG;
        const float* e2 = g_embW + tk2*GG;
        const float* e3 = g_embW + tk3*GG;
        float er0 = __ldg(e0+j),    er1 = __ldg(e1+j),    er2 = __ldg(e2+j),    er3 = __ldg(e3+j);
        float ez0 = __ldg(e0+32+j), ez1 = __ldg(e1+32+j), ez2 = __ldg(e2+32+j), ez3 = __ldg(e3+32+j);
        float en0 = __ldg(e0+64+j), en1 = __ldg(e1+64+j), en2 = __ldg(e2+64+j), en3 = __ldg(e3+64+j);

        // ---- cached flag poll + issue pv loads (consumed after h-side) ----
        float p0=0.f, p1=0.f, p2=0.f, p3=0.f;
        if (r > 0) {
            if (flag_cache <= t) {
                do { flag_cache = ld_acquire(pf); } while (flag_cache <= t);
            }
            p0 = __ldcg(pr0 + t*HH + j);
            p1 = __ldcg(pr1 + t*HH + j);
            p2 = __ldcg(pr2 + t*HH + j);
            p3 = __ldcg(pr3 + t*HH + j);
        }

        // ---- layer 0: h-side first (hides pv/embW latency) ----
        float aR0=k0r, aR1=k0r, aR2=k0r, aR3=k0r;
        float aZ0=k0z, aZ1=k0z, aZ2=k0z, aZ3=k0z;
        float aM0=k0m, aM1=k0m, aM2=k0m, aM3=k0m;
        float aN0, aN1, aN2, aN3;
        SIDE1(W_h0, S_h0, aM0,aM1,aM2,aM3)

        // fold in embW; then x-side (M @ pv)
        aR0 += er0; aR1 += er1; aR2 += er2; aR3 += er3;
        aZ0 += ez0; aZ1 += ez1; aZ2 += ez2; aZ3 += ez3;
        aN0 = k0n + en0; aN1 = k0n + en1; aN2 = k0n + en2; aN3 = k0n + en3;
        if (r > 0) {
            __syncwarp();
            S_pv[j]    = make_float2(p0, p1);
            S_pv[32+j] = make_float2(p2, p3);
            __syncwarp();
            SIDE1(W_M, S_pv, aN0,aN1,aN2,aN3)
        }
        GRU4(h0_0,h0_1,h0_2,h0_3, S_h0)

        // ---- layer 1 ----
        aR0=k1r; aR1=k1r; aR2=k1r; aR3=k1r;
        aZ0=k1z; aZ1=k1z; aZ2=k1z; aZ3=k1z;
        aN0=k1n; aN1=k1n; aN2=k1n; aN3=k1n;
        aM0=k1m; aM1=k1m; aM2=k1m; aM3=k1m;
        SIDE1(W_i1, S_h0, aN0,aN1,aN2,aN3)
        SIDE1(W_h1, S_h1, aM0,aM1,aM2,aM3)
        GRU4(h1_0,h1_1,h1_2,h1_3, S_h1)

        // ---- layer 2 ----
        aR0=k2r; aR1=k2r; aR2=k2r; aR3=k2r;
        aZ0=k2z; aZ1=k2z; aZ2=k2z; aZ3=k2z;
        aN0=k2n; aN1=k2n; aN2=k2n; aN3=k2n;
        aM0=k2m; aM1=k2m; aM2=k2m; aM3=k2m;
        SIDE1(W_i2, S_h1, aN0,aN1,aN2,aN3)
        SIDE1(W_h2, S_h2, aM0,aM1,aM2,aM3)
        GRU4(h2_0,h2_1,h2_2,h2_3, S_h2)

        // ---- publish top-layer output + flag (release) ----
        __stcg(out0 + t*HH + j, h2_0);
        __stcg(out1 + t*HH + j, h2_1);
        __stcg(out2 + t*HH + j, h2_2);
        __stcg(out3 + t*HH + j, h2_3);
        __syncwarp();
        if (j == 0) st_release(pub, t + 1);
    }
}

// -------- kernel 3: output projection (8 tokens per warp) --------
__global__ void __launch_bounds__(256) proj_kernel(
    const float* __restrict__ wout,   // [258][32]
    const float* __restrict__ bout,   // [258]
    float* __restrict__ pred)         // [262144][258]
{
    __shared__ float ws[32][264];
    __shared__ float bs[288];
    int tid = threadIdx.x;
    for (int i = tid; i < NV*HH; i += 256) {
        int v = i >> 5, h = i & 31;
        ws[h][v] = wout[i];
    }
    for (int i = tid; i < NV; i += 256) bs[i] = bout[i];
    __syncthreads();

    int warp = tid >> 5, lane = tid & 31;
    int tok0 = (blockIdx.x*8 + warp) * 8;

    float hv[8];
    #pragma unroll
    for (int i = 0; i < 8; ++i) hv[i] = g_h[(size_t)(tok0+i)*HH + lane];

    float acc[8][9];
    #pragma unroll
    for (int k = 0; k < 9; ++k) {
        int v = lane + 32*k;
        float b = (v < NV) ? bs[v] : 0.f;
        #pragma unroll
        for (int i = 0; i < 8; ++i) acc[i][k] = b;
    }
    #pragma unroll 4
    for (int h = 0; h < 32; ++h) {
        float wv[9];
        #pragma unroll
        for (int k = 0; k < 9; ++k) { int v = lane + 32*k; wv[k] = (v < NV) ? ws[h][v] : 0.f; }
        #pragma unroll
        for (int i = 0; i < 8; ++i) {
            float hb = __shfl_sync(0xffffffffu, hv[i], h);
            #pragma unroll
            for (int k = 0; k < 9; ++k) acc[i][k] = fmaf(wv[k], hb, acc[i][k]);
        }
    }
    #pragma unroll
    for (int i = 0; i < 8; ++i) {
        size_t base = (size_t)(tok0+i)*NV;
        #pragma unroll
        for (int k = 0; k < 9; ++k) { int v = lane + 32*k; if (v < NV) pred[base + v] = acc[i][k]; }
    }
}

// -------- launch --------
extern "C" void kernel_launch(void* const* d_in, const int* in_sizes, int n_in,
                              void* d_out, int out_size)
{
    const int*   x    = (const int*)  d_in[0];
    const float* emb  = (const float*)d_in[1];
    const float* wih0 = (const float*)d_in[2];
    const float* whh0 = (const float*)d_in[3];
    const float* bih0 = (const float*)d_in[4];
    const float* bhh0 = (const float*)d_in[5];
    const float* bih1v = (const float*)d_in[8];
    const float* wih1 = (const float*)d_in[6];
    const float* whh1 = (const float*)d_in[7];
    const float* bhh1 = (const float*)d_in[9];
    const float* wih2 = (const float*)d_in[10];
    const float* whh2 = (const float*)d_in[11];
    const float* bih2 = (const float*)d_in[12];
    const float* bhh2 = (const float*)d_in[13];
    const float* wh2e = (const float*)d_in[14];
    const float* bh2e = (const float*)d_in[15];
    const float* wout = (const float*)d_in[16];
    const float* bout = (const float*)d_in[17];
    float* pred = (float*)d_out;

    // smem: weights 82944 B + stages 8192 B + tokens 8192 B = 99328 B
    const int smem_bytes = (6*MSIZE + 2048 + 2048) * (int)sizeof(float);
    cudaFuncSetAttribute(wave_kernel, cudaFuncAttributeMaxDynamicSharedMemorySize, smem_bytes);

    zero_flag_kernel<<<2, 256>>>();
    precompute_kernel<<<NV + 6, GG>>>(emb, wih0, bih0, wh2e, bh2e,
                                      whh0, wih1, whh1, wih2, whh2);
    wave_kernel<<<RS, 128, smem_bytes>>>(x, bhh0, bih1v, bhh1, bih2, bhh2);
    proj_kernel<<<NTOK/64, 256>>>(wout, bout, pred);
}

// round 10
// speedup vs baseline: 1.6331x; 1.0781x over previous
#include <cuda_runtime.h>
#include <cstdint>

// Fixed shapes
#define BB    16
#define RS    128
#define TT    128
#define HH    32
#define GG    96
#define NV    258
#define NTOK  (BB*RS*TT)     // 262144
#define RPAD  36             // padded row length (floats) for weight rows
#define MSIZE (GG*RPAD)      // 3456 floats per matrix

// -------- device scratch --------
__device__ float g_embW[NV*GG];           // W_ih0[:, :64] @ embed^T -> [258][96]
__device__ float g_Wp[6*MSIZE];           // 0:M 1:Wh0 2:Wi1 3:Wh1 4:Wi2 5:Wh2  ([96][36] rows)
__device__ float g_base[GG];              // b_ih0 + Wih0 @ b_h2e
__device__ float g_w64[GG];               // Wih0[:,64]
__device__ float g_h[(size_t)NTOK*HH];    // top-layer outputs [B][R][T][H]
__device__ int   g_flag[RS*8];            // per (row, warp) progress

// -------- helpers --------
__device__ __forceinline__ float sigf(float x)   { return __fdividef(1.0f, 1.0f + __expf(-x)); }
__device__ __forceinline__ float tanh_f(float x) { return __fdividef(2.0f, 1.0f + __expf(-2.0f*x)) - 1.0f; }

__device__ __forceinline__ void st_release(int* p, int v) {
    asm volatile("st.release.gpu.global.s32 [%0], %1;" :: "l"(p), "r"(v) : "memory");
}
__device__ __forceinline__ int ld_acquire(const int* p) {
    int v;
    asm volatile("ld.acquire.gpu.global.s32 %0, [%1];" : "=r"(v) : "l"(p) : "memory");
    return v;
}

// -------- kernel 0: zero flags --------
__global__ void zero_flag_kernel() {
    int i = blockIdx.x*blockDim.x + threadIdx.x;
    if (i < RS*8) g_flag[i] = 0;
}

// -------- kernel 1: precompute folded weights --------
__global__ void precompute_kernel(
    const float* __restrict__ emb,   // [258][64]
    const float* __restrict__ wih0,  // [96][65]
    const float* __restrict__ bih0,  // [96]
    const float* __restrict__ wh2e,  // [65][32]
    const float* __restrict__ bh2e,  // [65]
    const float* __restrict__ whh0,  // [96][32]
    const float* __restrict__ wih1,  // [96][32]
    const float* __restrict__ whh1,
    const float* __restrict__ wih2,
    const float* __restrict__ whh2)
{
    int g = threadIdx.x;     // 0..95
    int blk = blockIdx.x;
    if (blk < NV) {
        float s = 0.f;
        #pragma unroll
        for (int e = 0; e < 64; ++e) s = fmaf(wih0[g*65+e], emb[blk*64+e], s);
        g_embW[blk*GG + g] = s;
    } else if (blk == NV) {
        for (int k = 0; k < HH; ++k) {
            float s = 0.f;
            for (int i = 0; i < 65; ++i) s = fmaf(wih0[g*65+i], wh2e[i*HH+k], s);
            g_Wp[g*RPAD + k] = s;            // M = Wih0[:, :65] @ Wh2e
        }
        float s = 0.f;
        for (int i = 0; i < 65; ++i) s = fmaf(wih0[g*65+i], bh2e[i], s);
        g_base[g] = bih0[g] + s;
        g_w64[g]  = wih0[g*65 + 64];
    } else {
        int m = blk - NV - 1;   // 0..4 -> Wh0, Wi1, Wh1, Wi2, Wh2
        const float* w = (m==0)?whh0 : (m==1)?wih1 : (m==2)?whh1 : (m==3)?wih2 : whh2;
        for (int k = 0; k < HH; ++k)
            g_Wp[(1+m)*MSIZE + g*RPAD + k] = w[g*HH + k];
    }
}

// 6 FMAs: one k-slice, 2 batches; r/z into aR/aZ, n into named targets
#define FG2(wr_,wz_,wn_, v0,v1, N0,N1) \
    aR0=fmaf(wr_,v0,aR0); aR1=fmaf(wr_,v1,aR1); \
    aZ0=fmaf(wz_,v0,aZ0); aZ1=fmaf(wz_,v1,aZ1); \
    N0 =fmaf(wn_,v0,N0);  N1 =fmaf(wn_,v1,N1);

// one matvec side: 3 gate rows x 32 k x 2 batches. W: smem float base;
// S: float2* stage [32] (S[k]=(b0,b1)). n-target selectable.
#define SIDE2(W, S, N0,N1) { \
    const float4* S4 = (const float4*)(S); \
    _Pragma("unroll") \
    for (int kq = 0; kq < 8; ++kq) { \
        float4 wr = *(const float4*)((W)+rowR+kq*4); \
        float4 wz = *(const float4*)((W)+rowZ+kq*4); \
        float4 wn = *(const float4*)((W)+rowN+kq*4); \
        float4 xa = S4[2*kq], xb = S4[2*kq+1]; \
        FG2(wr.x,wz.x,wn.x, xa.x,xa.y, N0,N1) \
        FG2(wr.y,wz.y,wn.y, xa.z,xa.w, N0,N1) \
        FG2(wr.z,wz.z,wn.z, xb.x,xb.y, N0,N1) \
        FG2(wr.w,wz.w,wn.w, xb.z,xb.w, N0,N1) \
    } }

#define GRUUP(h, aR, aZ, aNi, aNh) { \
    float rg = sigf(aR); float zg = sigf(aZ); \
    float ng = tanh_f(aNi + rg*(aNh)); \
    h = fmaf(zg, (h) - ng, ng); }

#define GRU2(H0,H1, SDST) { \
    GRUUP(H0, aR0, aZ0, aN0, aM0) \
    GRUUP(H1, aR1, aZ1, aN1, aM1) \
    __syncwarp(); \
    (SDST)[j] = make_float2(H0, H1); \
    __syncwarp(); }

// -------- kernel 2: wavefront GRU --------
// grid = 128 CTAs (one per row), 256 threads = 8 warps (2/SMSP), warp w owns
// batches 2w, 2w+1. Cross-row sync via per-(row,warp) release/acquire flags.
__global__ void __launch_bounds__(256, 1) wave_kernel(
    const int*   __restrict__ x,
    const float* __restrict__ bhh0, const float* __restrict__ bih1,
    const float* __restrict__ bhh1, const float* __restrict__ bih2,
    const float* __restrict__ bhh2)
{
    extern __shared__ float sm[];
    float*  sW   = sm;                              // 6*MSIZE floats (82944 B)
    float2* stg  = (float2*)(sm + 6*MSIZE);         // 8 warps * 4 stages * 32 float2 (8192 B)
    int*    stok = (int*)(sm + 6*MSIZE + 2048);     // 16*128 tokens (8192 B)

    const int tid = threadIdx.x;
    const int r   = blockIdx.x;
    const int w   = tid >> 5;
    const int j   = tid & 31;

    {   // stage weights, zero stages, stage tokens
        const float4* src = (const float4*)g_Wp;
        float4* dst = (float4*)sW;
        for (int i = tid; i < 6*MSIZE/4; i += 256) dst[i] = src[i];
        for (int i = tid; i < 1024; i += 256) stg[i] = make_float2(0.f, 0.f);
        for (int i = tid; i < BB*TT; i += 256) {
            int b = i >> 7, tt = i & 127;
            stok[i] = x[(b*RS + r)*TT + tt];
        }
    }
    __syncthreads();

    const int rowR = j*RPAD, rowZ = (32+j)*RPAD, rowN = (64+j)*RPAD;
    const float* W_M  = sW;
    const float* W_h0 = sW + 1*MSIZE;
    const float* W_i1 = sW + 2*MSIZE;
    const float* W_h1 = sW + 3*MSIZE;
    const float* W_i2 = sW + 4*MSIZE;
    const float* W_h2 = sW + 5*MSIZE;

    float2* S_pv = stg + w*128;        // 4 stages of 32 float2 per warp
    float2* S_h0 = S_pv + 32;
    float2* S_h1 = S_pv + 64;
    float2* S_h2 = S_pv + 96;

    const float rowpos = (float)r * (1.0f/64.0f) - 1.0f;
    const float k0r  = g_base[j]    + g_w64[j]   *rowpos + bhh0[j];
    const float k0z  = g_base[32+j] + g_w64[32+j]*rowpos + bhh0[32+j];
    const float k0n  = g_base[64+j] + g_w64[64+j]*rowpos;
    const float k0m  = bhh0[64+j];
    const float k1r  = bih1[j] + bhh1[j];
    const float k1z  = bih1[32+j] + bhh1[32+j];
    const float k1n  = bih1[64+j];
    const float k1m  = bhh1[64+j];
    const float k2r  = bih2[j] + bhh2[j];
    const float k2z  = bih2[32+j] + bhh2[32+j];
    const float k2n  = bih2[64+j];
    const float k2m  = bhh2[64+j];

    const int b0 = w*2;
    float* out0 = g_h + (size_t)((b0+0)*RS + r)*TT*HH;
    float* out1 = g_h + (size_t)((b0+1)*RS + r)*TT*HH;
    const int rp = (r > 0) ? (r-1) : 0;
    const float* pr0 = g_h + (size_t)((b0+0)*RS + rp)*TT*HH;
    const float* pr1 = g_h + (size_t)((b0+1)*RS + rp)*TT*HH;
    int*       pub = &g_flag[r*8 + w];
    const int* pf  = &g_flag[rp*8 + w];

    float h0_0=0.f,h0_1=0.f;
    float h1_0=0.f,h1_1=0.f;
    float h2_0=0.f,h2_1=0.f;

    int flag_cache = 0;   // cached producer progress (acquire-loaded)

    for (int t = 0; t < TT; ++t) {
        // ---- issue embW loads early (consumed only after layer-0 h-side) ----
        const int tk0 = stok[(b0+0)*TT + t];
        const int tk1 = stok[(b0+1)*TT + t];
        const float* e0 = g_embW + tk0*GG;
        const float* e1 = g_embW + tk1*GG;
        float er0 = __ldg(e0+j),    er1 = __ldg(e1+j);
        float ez0 = __ldg(e0+32+j), ez1 = __ldg(e1+32+j);
        float en0 = __ldg(e0+64+j), en1 = __ldg(e1+64+j);

        // ---- cached flag poll + issue pv loads (consumed after h-side) ----
        float p0=0.f, p1=0.f;
        if (r > 0) {
            if (flag_cache <= t) {
                do { flag_cache = ld_acquire(pf); } while (flag_cache <= t);
            }
            p0 = __ldcg(pr0 + t*HH + j);
            p1 = __ldcg(pr1 + t*HH + j);
        }

        // ---- layer 0: h-side first (hides pv/embW latency) ----
        float aR0=k0r, aR1=k0r;
        float aZ0=k0z, aZ1=k0z;
        float aM0=k0m, aM1=k0m;
        float aN0, aN1;
        SIDE2(W_h0, S_h0, aM0,aM1)

        // fold in embW; then x-side (M @ pv)
        aR0 += er0; aR1 += er1;
        aZ0 += ez0; aZ1 += ez1;
        aN0 = k0n + en0; aN1 = k0n + en1;
        if (r > 0) {
            __syncwarp();
            S_pv[j] = make_float2(p0, p1);
            __syncwarp();
            SIDE2(W_M, S_pv, aN0,aN1)
        }
        GRU2(h0_0,h0_1, S_h0)

        // ---- layer 1 ----
        aR0=k1r; aR1=k1r;
        aZ0=k1z; aZ1=k1z;
        aN0=k1n; aN1=k1n;
        aM0=k1m; aM1=k1m;
        SIDE2(W_i1, S_h0, aN0,aN1)
        SIDE2(W_h1, S_h1, aM0,aM1)
        GRU2(h1_0,h1_1, S_h1)

        // ---- layer 2 ----
        aR0=k2r; aR1=k2r;
        aZ0=k2z; aZ1=k2z;
        aN0=k2n; aN1=k2n;
        aM0=k2m; aM1=k2m;
        SIDE2(W_i2, S_h1, aN0,aN1)
        SIDE2(W_h2, S_h2, aM0,aM1)
        GRU2(h2_0,h2_1, S_h2)

        // ---- publish top-layer output + flag (release) ----
        __stcg(out0 + t*HH + j, h2_0);
        __stcg(out1 + t*HH + j, h2_1);
        __syncwarp();
        if (j == 0) st_release(pub, t + 1);
    }
}

// -------- kernel 3: output projection (8 tokens per warp) --------
__global__ void __launch_bounds__(256) proj_kernel(
    const float* __restrict__ wout,   // [258][32]
    const float* __restrict__ bout,   // [258]
    float* __restrict__ pred)         // [262144][258]
{
    __shared__ float ws[32][264];
    __shared__ float bs[288];
    int tid = threadIdx.x;
    for (int i = tid; i < NV*HH; i += 256) {
        int v = i >> 5, h = i & 31;
        ws[h][v] = wout[i];
    }
    for (int i = tid; i < NV; i += 256) bs[i] = bout[i];
    __syncthreads();

    int warp = tid >> 5, lane = tid & 31;
    int tok0 = (blockIdx.x*8 + warp) * 8;

    float hv[8];
    #pragma unroll
    for (int i = 0; i < 8; ++i) hv[i] = g_h[(size_t)(tok0+i)*HH + lane];

    float acc[8][9];
    #pragma unroll
    for (int k = 0; k < 9; ++k) {
        int v = lane + 32*k;
        float b = (v < NV) ? bs[v] : 0.f;
        #pragma unroll
        for (int i = 0; i < 8; ++i) acc[i][k] = b;
    }
    #pragma unroll 4
    for (int h = 0; h < 32; ++h) {
        float wv[9];
        #pragma unroll
        for (int k = 0; k < 9; ++k) { int v = lane + 32*k; wv[k] = (v < NV) ? ws[h][v] : 0.f; }
        #pragma unroll
        for (int i = 0; i < 8; ++i) {
            float hb = __shfl_sync(0xffffffffu, hv[i], h);
            #pragma unroll
            for (int k = 0; k < 9; ++k) acc[i][k] = fmaf(wv[k], hb, acc[i][k]);
        }
    }
    #pragma unroll
    for (int i = 0; i < 8; ++i) {
        size_t base = (size_t)(tok0+i)*NV;
        #pragma unroll
        for (int k = 0; k < 9; ++k) { int v = lane + 32*k; if (v < NV) pred[base + v] = acc[i][k]; }
    }
}

// -------- launch --------
extern "C" void kernel_launch(void* const* d_in, const int* in_sizes, int n_in,
                              void* d_out, int out_size)
{
    const int*   x    = (const int*)  d_in[0];
    const float* emb  = (const float*)d_in[1];
    const float* wih0 = (const float*)d_in[2];
    const float* whh0 = (const float*)d_in[3];
    const float* bih0 = (const float*)d_in[4];
    const float* bhh0 = (const float*)d_in[5];
    const float* wih1 = (const float*)d_in[6];
    const float* whh1 = (const float*)d_in[7];
    const float* bih1 = (const float*)d_in[8];
    const float* bhh1 = (const float*)d_in[9];
    const float* wih2 = (const float*)d_in[10];
    const float* whh2 = (const float*)d_in[11];
    const float* bih2 = (const float*)d_in[12];
    const float* bhh2 = (const float*)d_in[13];
    const float* wh2e = (const float*)d_in[14];
    const float* bh2e = (const float*)d_in[15];
    const float* wout = (const float*)d_in[16];
    const float* bout = (const float*)d_in[17];
    float* pred = (float*)d_out;

    // smem: weights 82944 B + stages 8192 B + tokens 8192 B = 99328 B
    const int smem_bytes = (6*MSIZE + 2048 + 2048) * (int)sizeof(float);
    cudaFuncSetAttribute(wave_kernel, cudaFuncAttributeMaxDynamicSharedMemorySize, smem_bytes);

    zero_flag_kernel<<<4, 256>>>();
    precompute_kernel<<<NV + 6, GG>>>(emb, wih0, bih0, wh2e, bh2e,
                                      whh0, wih1, whh1, wih2, whh2);
    wave_kernel<<<RS, 256, smem_bytes>>>(x, bhh0, bih1, bhh1, bih2, bhh2);
    proj_kernel<<<NTOK/64, 256>>>(wout, bout, pred);
}

// round 12
// speedup vs baseline: 1.6885x; 1.0339x over previous
#include <cuda_runtime.h>
#include <cstdint>

// Fixed shapes
#define BB    16
#define RS    128
#define TT    128
#define HH    32
#define GG    96
#define NV    258
#define NTOK  (BB*RS*TT)     // 262144
#define RPAD  36             // padded row length (floats) for weight rows
#define MSIZE (GG*RPAD)      // 3456 floats per matrix

typedef unsigned long long u64;

// -------- device scratch --------
__device__ float g_embW[NV*GG];           // W_ih0[:, :64] @ embed^T -> [258][96]
__device__ float g_Wp[6*MSIZE];           // 0:M 1:Wh0 2:Wi1 3:Wh1 4:Wi2 5:Wh2  ([96][36] rows)
__device__ float g_base[GG];              // b_ih0 + Wih0 @ b_h2e
__device__ float g_w64[GG];               // Wih0[:,64]
__device__ float g_h[(size_t)NTOK*HH];    // top-layer outputs [B][R][T][H]
__device__ int   g_flag[RS*4];            // per (row, warp) progress

// -------- helpers --------
__device__ __forceinline__ float sigf(float x)   { return __fdividef(1.0f, 1.0f + __expf(-x)); }
__device__ __forceinline__ float tanh_f(float x) { return __fdividef(2.0f, 1.0f + __expf(-2.0f*x)) - 1.0f; }

__device__ __forceinline__ void st_release(int* p, int v) {
    asm volatile("st.release.gpu.global.s32 [%0], %1;" :: "l"(p), "r"(v) : "memory");
}
__device__ __forceinline__ int ld_acquire(const int* p) {
    int v;
    asm volatile("ld.acquire.gpu.global.s32 %0, [%1];" : "=r"(v) : "l"(p) : "memory");
    return v;
}

// f32x2 packed ops (both operands naturally packed -> no dup movs)
#define FMA2(d,a,b) asm("fma.rn.f32x2 %0, %1, %2, %0;" : "+l"(d) : "l"(a), "l"(b))
#define ADD2(d,b)   asm("add.rn.f32x2 %0, %0, %1;"     : "+l"(d) : "l"(b))
#define PACK2(o,lo,hi) asm("mov.b64 %0, {%1, %2};" : "=l"(o) : "r"(__float_as_uint(lo)), "r"(__float_as_uint(hi)))
#define FOLDF(out, acc) { unsigned _l,_h; asm("mov.b64 {%0, %1}, %2;" : "=r"(_l), "=r"(_h) : "l"(acc)); \
                          out = __uint_as_float(_l) + __uint_as_float(_h); }

// -------- kernel 0: zero flags --------
__global__ void zero_flag_kernel() {
    int i = blockIdx.x*blockDim.x + threadIdx.x;
    if (i < RS*4) g_flag[i] = 0;
}

// -------- kernel 1: precompute folded weights --------
__global__ void precompute_kernel(
    const float* __restrict__ emb,   // [258][64]
    const float* __restrict__ wih0,  // [96][65]
    const float* __restrict__ bih0,  // [96]
    const float* __restrict__ wh2e,  // [65][32]
    const float* __restrict__ bh2e,  // [65]
    const float* __restrict__ whh0,  // [96][32]
    const float* __restrict__ wih1,  // [96][32]
    const float* __restrict__ whh1,
    const float* __restrict__ wih2,
    const float* __restrict__ whh2)
{
    int g = threadIdx.x;     // 0..95
    int blk = blockIdx.x;
    if (blk < NV) {
        float s = 0.f;
        #pragma unroll
        for (int e = 0; e < 64; ++e) s = fmaf(wih0[g*65+e], emb[blk*64+e], s);
        g_embW[blk*GG + g] = s;
    } else if (blk == NV) {
        for (int k = 0; k < HH; ++k) {
            float s = 0.f;
            for (int i = 0; i < 65; ++i) s = fmaf(wih0[g*65+i], wh2e[i*HH+k], s);
            g_Wp[g*RPAD + k] = s;            // M = Wih0[:, :65] @ Wh2e
        }
        float s = 0.f;
        for (int i = 0; i < 65; ++i) s = fmaf(wih0[g*65+i], bh2e[i], s);
        g_base[g] = bih0[g] + s;
        g_w64[g]  = wih0[g*65 + 64];
    } else {
        int m = blk - NV - 1;   // 0..4 -> Wh0, Wi1, Wh1, Wi2, Wh2
        const float* w = (m==0)?whh0 : (m==1)?wih1 : (m==2)?whh1 : (m==3)?wih2 : whh2;
        for (int k = 0; k < HH; ++k)
            g_Wp[(1+m)*MSIZE + g*RPAD + k] = w[g*HH + k];
    }
}

// 4 packed FMAs across batches for one weight pair
#define PFG(wv, x0,x1,x2,x3, A0,A1,A2,A3) \
    FMA2(A0,wv,x0); FMA2(A1,wv,x1); FMA2(A2,wv,x2); FMA2(A3,wv,x3);

// one matvec side: 3 gate rows x 32 k x 4 batches; even/odd-k pair accumulators.
// W: smem float base (row-major, lane j owns rows j/32+j/64+j).
// S: float* stage [4 batches][32 k] (broadcast reads). n-gate target selectable.
#define PSIDE(W, S, N0,N1,N2,N3) { \
  _Pragma("unroll") \
  for (int kq = 0; kq < 8; ++kq) { \
    ulonglong2 wr = *(const ulonglong2*)((W)+rowR+kq*4); \
    ulonglong2 wz = *(const ulonglong2*)((W)+rowZ+kq*4); \
    ulonglong2 wn = *(const ulonglong2*)((W)+rowN+kq*4); \
    ulonglong2 x0 = *(const ulonglong2*)((S)+ 0+kq*4); \
    ulonglong2 x1 = *(const ulonglong2*)((S)+32+kq*4); \
    ulonglong2 x2 = *(const ulonglong2*)((S)+64+kq*4); \
    ulonglong2 x3 = *(const ulonglong2*)((S)+96+kq*4); \
    PFG(wr.x, x0.x,x1.x,x2.x,x3.x, aR0,aR1,aR2,aR3) \
    PFG(wz.x, x0.x,x1.x,x2.x,x3.x, aZ0,aZ1,aZ2,aZ3) \
    PFG(wn.x, x0.x,x1.x,x2.x,x3.x, N0,N1,N2,N3) \
    PFG(wr.y, x0.y,x1.y,x2.y,x3.y, aR0,aR1,aR2,aR3) \
    PFG(wz.y, x0.y,x1.y,x2.y,x3.y, aZ0,aZ1,aZ2,aZ3) \
    PFG(wn.y, x0.y,x1.y,x2.y,x3.y, N0,N1,N2,N3) \
  } }

// fold pair accums -> GRU update for one batch
#define GRU1(H, AR,AZ,AN,AM) { \
    float fr,fz,fn,fm; FOLDF(fr,AR) FOLDF(fz,AZ) FOLDF(fn,AN) FOLDF(fm,AM) \
    float rg = sigf(fr); float zg = sigf(fz); \
    float ng = tanh_f(fn + rg*fm); \
    H = fmaf(zg, (H) - ng, ng); }

#define GRU4W(H0,H1,H2,H3, SDST) { \
    GRU1(H0, aR0,aZ0,aN0,aM0) \
    GRU1(H1, aR1,aZ1,aN1,aM1) \
    GRU1(H2, aR2,aZ2,aN2,aM2) \
    GRU1(H3, aR3,aZ3,aN3,aM3) \
    __syncwarp(); \
    (SDST)[j] = H0; (SDST)[32+j] = H1; (SDST)[64+j] = H2; (SDST)[96+j] = H3; \
    __syncwarp(); }

// -------- kernel 2: wavefront GRU --------
// grid = 128 CTAs (one per row), 128 threads = 4 warps, warp w owns batches 4w..4w+3.
__global__ void __launch_bounds__(128, 1) wave_kernel(
    const int*   __restrict__ x,
    const float* __restrict__ bhh0, const float* __restrict__ bih1,
    const float* __restrict__ bhh1, const float* __restrict__ bih2,
    const float* __restrict__ bhh2)
{
    extern __shared__ float sm[];
    float* sW   = sm;                             // 6*MSIZE floats (82944 B)
    float* stg  = sm + 6*MSIZE;                   // 4 warps * 4 stages * 128 floats (8192 B)
    int*   stok = (int*)(sm + 6*MSIZE + 2048);    // 16*128 tokens (8192 B)

    const int tid = threadIdx.x;
    const int r   = blockIdx.x;
    const int w   = tid >> 5;
    const int j   = tid & 31;

    {   // stage weights, zero stages, stage tokens
        const float4* src = (const float4*)g_Wp;
        float4* dst = (float4*)sW;
        for (int i = tid; i < 6*MSIZE/4; i += 128) dst[i] = src[i];
        for (int i = tid; i < 2048; i += 128) stg[i] = 0.f;
        for (int i = tid; i < BB*TT; i += 128) {
            int b = i >> 7, tt = i & 127;
            stok[i] = x[(b*RS + r)*TT + tt];
        }
    }
    __syncthreads();

    const int rowR = j*RPAD, rowZ = (32+j)*RPAD, rowN = (64+j)*RPAD;
    const float* W_M  = sW;
    const float* W_h0 = sW + 1*MSIZE;
    const float* W_i1 = sW + 2*MSIZE;
    const float* W_h1 = sW + 3*MSIZE;
    const float* W_i2 = sW + 4*MSIZE;
    const float* W_h2 = sW + 5*MSIZE;

    float* S_pv = stg + w*512;      // [batch][32] layout per stage
    float* S_h0 = S_pv + 128;
    float* S_h1 = S_pv + 256;
    float* S_h2 = S_pv + 384;

    const float rowpos = (float)r * (1.0f/64.0f) - 1.0f;
    const float k0r  = g_base[j]    + g_w64[j]   *rowpos + bhh0[j];
    const float k0z  = g_base[32+j] + g_w64[32+j]*rowpos + bhh0[32+j];
    const float k0n  = g_base[64+j] + g_w64[64+j]*rowpos;
    const float k0m  = bhh0[64+j];
    const float k1r  = bih1[j] + bhh1[j];
    const float k1z  = bih1[32+j] + bhh1[32+j];
    const float k1n  = bih1[64+j];
    const float k1m  = bhh1[64+j];
    const float k2r  = bih2[j] + bhh2[j];
    const float k2z  = bih2[32+j] + bhh2[32+j];
    const float k2n  = bih2[64+j];
    const float k2m  = bhh2[64+j];

    const int b0 = w*4;
    float* out0 = g_h + (size_t)((b0+0)*RS + r)*TT*HH;
    float* out1 = g_h + (size_t)((b0+1)*RS + r)*TT*HH;
    float* out2 = g_h + (size_t)((b0+2)*RS + r)*TT*HH;
    float* out3 = g_h + (size_t)((b0+3)*RS + r)*TT*HH;
    const int rp = (r > 0) ? (r-1) : 0;
    const float* pr0 = g_h + (size_t)((b0+0)*RS + rp)*TT*HH;
    const float* pr1 = g_h + (size_t)((b0+1)*RS + rp)*TT*HH;
    const float* pr2 = g_h + (size_t)((b0+2)*RS + rp)*TT*HH;
    const float* pr3 = g_h + (size_t)((b0+3)*RS + rp)*TT*HH;
    int*       pub = &g_flag[r*4 + w];
    const int* pf  = &g_flag[rp*4 + w];

    float h0_0=0.f,h0_1=0.f,h0_2=0.f,h0_3=0.f;
    float h1_0=0.f,h1_1=0.f,h1_2=0.f,h1_3=0.f;
    float h2_0=0.f,h2_1=0.f,h2_2=0.f,h2_3=0.f;

    int flag_cache = 0;

    for (int t = 0; t < TT; ++t) {
        // ---- issue embW loads early (consumed only after layer-0 sides) ----
        const int tk0 = stok[(b0+0)*TT + t];
        const int tk1 = stok[(b0+1)*TT + t];
        const int tk2 = stok[(b0+2)*TT + t];
        const int tk3 = stok[(b0+3)*TT + t];
        const float* e0 = g_embW + tk0*GG;
        const float* e1 = g_embW + tk1*GG;
        const float* e2 = g_embW + tk2*GG;
        const float* e3 = g_embW + tk3*GG;
        float er0 = __ldg(e0+j),    er1 = __ldg(e1+j),    er2 = __ldg(e2+j),    er3 = __ldg(e3+j);
        float ez0 = __ldg(e0+32+j), ez1 = __ldg(e1+32+j), ez2 = __ldg(e2+32+j), ez3 = __ldg(e3+32+j);
        float en0 = __ldg(e0+64+j), en1 = __ldg(e1+64+j), en2 = __ldg(e2+64+j), en3 = __ldg(e3+64+j);

        // ---- cached flag poll + issue pv loads (consumed after h-side) ----
        float p0=0.f, p1=0.f, p2=0.f, p3=0.f;
        if (r > 0) {
            if (flag_cache <= t) {
                do { flag_cache = ld_acquire(pf); } while (flag_cache <= t);
            }
            p0 = __ldcg(pr0 + t*HH + j);
            p1 = __ldcg(pr1 + t*HH + j);
            p2 = __ldcg(pr2 + t*HH + j);
            p3 = __ldcg(pr3 + t*HH + j);
        }

        // ---- layer 0: h-side first (hides pv/embW latency) ----
        u64 aR0,aR1,aR2,aR3, aZ0,aZ1,aZ2,aZ3, aN0,aN1,aN2,aN3, aM0,aM1,aM2,aM3;
        PACK2(aR0,k0r,0.f); PACK2(aR1,k0r,0.f); PACK2(aR2,k0r,0.f); PACK2(aR3,k0r,0.f);
        PACK2(aZ0,k0z,0.f); PACK2(aZ1,k0z,0.f); PACK2(aZ2,k0z,0.f); PACK2(aZ3,k0z,0.f);
        PACK2(aM0,k0m,0.f); PACK2(aM1,k0m,0.f); PACK2(aM2,k0m,0.f); PACK2(aM3,k0m,0.f);
        PSIDE(W_h0, S_h0, aM0,aM1,aM2,aM3)

        // fold embW into accumulators (loads have returned); then x-side (M @ pv)
        PACK2(aN0, k0n+en0, 0.f); PACK2(aN1, k0n+en1, 0.f);
        PACK2(aN2, k0n+en2, 0.f); PACK2(aN3, k0n+en3, 0.f);
        {
            u64 tv;
            PACK2(tv, er0, 0.f); ADD2(aR0, tv); PACK2(tv, er1, 0.f); ADD2(aR1, tv);
            PACK2(tv, er2, 0.f); ADD2(aR2, tv); PACK2(tv, er3, 0.f); ADD2(aR3, tv);
            PACK2(tv, ez0, 0.f); ADD2(aZ0, tv); PACK2(tv, ez1, 0.f); ADD2(aZ1, tv);
            PACK2(tv, ez2, 0.f); ADD2(aZ2, tv); PACK2(tv, ez3, 0.f); ADD2(aZ3, tv);
        }
        if (r > 0) {
            __syncwarp();
            S_pv[j] = p0; S_pv[32+j] = p1; S_pv[64+j] = p2; S_pv[96+j] = p3;
            __syncwarp();
            PSIDE(W_M, S_pv, aN0,aN1,aN2,aN3)
        }
        GRU4W(h0_0,h0_1,h0_2,h0_3, S_h0)

        // ---- layer 1 ----
        PACK2(aR0,k1r,0.f); PACK2(aR1,k1r,0.f); PACK2(aR2,k1r,0.f); PACK2(aR3,k1r,0.f);
        PACK2(aZ0,k1z,0.f); PACK2(aZ1,k1z,0.f); PACK2(aZ2,k1z,0.f); PACK2(aZ3,k1z,0.f);
        PACK2(aN0,k1n,0.f); PACK2(aN1,k1n,0.f); PACK2(aN2,k1n,0.f); PACK2(aN3,k1n,0.f);
        PACK2(aM0,k1m,0.f); PACK2(aM1,k1m,0.f); PACK2(aM2,k1m,0.f); PACK2(aM3,k1m,0.f);
        PSIDE(W_i1, S_h0, aN0,aN1,aN2,aN3)
        PSIDE(W_h1, S_h1, aM0,aM1,aM2,aM3)
        GRU4W(h1_0,h1_1,h1_2,h1_3, S_h1)

        // ---- layer 2 ----
        PACK2(aR0,k2r,0.f); PACK2(aR1,k2r,0.f); PACK2(aR2,k2r,0.f); PACK2(aR3,k2r,0.f);
        PACK2(aZ0,k2z,0.f); PACK2(aZ1,k2z,0.f); PACK2(aZ2,k2z,0.f); PACK2(aZ3,k2z,0.f);
        PACK2(aN0,k2n,0.f); PACK2(aN1,k2n,0.f); PACK2(aN2,k2n,0.f); PACK2(aN3,k2n,0.f);
        PACK2(aM0,k2m,0.f); PACK2(aM1,k2m,0.f); PACK2(aM2,k2m,0.f); PACK2(aM3,k2m,0.f);
        PSIDE(W_i2, S_h1, aN0,aN1,aN2,aN3)
        PSIDE(W_h2, S_h2, aM0,aM1,aM2,aM3)
        GRU4W(h2_0,h2_1,h2_2,h2_3, S_h2)

        // ---- publish top-layer output + flag (release) ----
        __stcg(out0 + t*HH + j, h2_0);
        __stcg(out1 + t*HH + j, h2_1);
        __stcg(out2 + t*HH + j, h2_2);
        __stcg(out3 + t*HH + j, h2_3);
        __syncwarp();
        if (j == 0) st_release(pub, t + 1);
    }
}

// -------- kernel 3: output projection (8 tokens per warp) --------
__global__ void __launch_bounds__(256) proj_kernel(
    const float* __restrict__ wout,   // [258][32]
    const float* __restrict__ bout,   // [258]
    float* __restrict__ pred)         // [262144][258]
{
    __shared__ float ws[32][264];
    __shared__ float bs[288];
    int tid = threadIdx.x;
    for (int i = tid; i < NV*HH; i += 256) {
        int v = i >> 5, h = i & 31;
        ws[h][v] = wout[i];
    }
    for (int i = tid; i < NV; i += 256) bs[i] = bout[i];
    __syncthreads();

    int warp = tid >> 5, lane = tid & 31;
    int tok0 = (blockIdx.x*8 + warp) * 8;

    float hv[8];
    #pragma unroll
    for (int i = 0; i < 8; ++i) hv[i] = g_h[(size_t)(tok0+i)*HH + lane];

    float acc[8][9];
    #pragma unroll
    for (int k = 0; k < 9; ++k) {
        int v = lane + 32*k;
        float b = (v < NV) ? bs[v] : 0.f;
        #pragma unroll
        for (int i = 0; i < 8; ++i) acc[i][k] = b;
    }
    #pragma unroll 4
    for (int h = 0; h < 32; ++h) {
        float wv[9];
        #pragma unroll
        for (int k = 0; k < 9; ++k) { int v = lane + 32*k; wv[k] = (v < NV) ? ws[h][v] : 0.f; }
        #pragma unroll
        for (int i = 0; i < 8; ++i) {
            float hb = __shfl_sync(0xffffffffu, hv[i], h);
            #pragma unroll
            for (int k = 0; k < 9; ++k) acc[i][k] = fmaf(wv[k], hb, acc[i][k]);
        }
    }
    #pragma unroll
    for (int i = 0; i < 8; ++i) {
        size_t base = (size_t)(tok0+i)*NV;
        #pragma unroll
        for (int k = 0; k < 9; ++k) { int v = lane + 32*k; if (v < NV) pred[base + v] = acc[i][k]; }
    }
}

// -------- launch --------
extern "C" void kernel_launch(void* const* d_in, const int* in_sizes, int n_in,
                              void* d_out, int out_size)
{
    const int*   x    = (const int*)  d_in[0];
    const float* emb  = (const float*)d_in[1];
    const float* wih0 = (const float*)d_in[2];
    const float* whh0 = (const float*)d_in[3];
    const float* bih0 = (const float*)d_in[4];
    const float* bhh0 = (const float*)d_in[5];
    const float* wih1 = (const float*)d_in[6];
    const float* whh1 = (const float*)d_in[7];
    const float* bih1 = (const float*)d_in[8];
    const float* bhh1 = (const float*)d_in[9];
    const float* wih2 = (const float*)d_in[10];
    const float* whh2 = (const float*)d_in[11];
    const float* bih2 = (const float*)d_in[12];
    const float* bhh2 = (const float*)d_in[13];
    const float* wh2e = (const float*)d_in[14];
    const float* bh2e = (const float*)d_in[15];
    const float* wout = (const float*)d_in[16];
    const float* bout = (const float*)d_in[17];
    float* pred = (float*)d_out;

    // smem: weights 82944 B + stages 8192 B + tokens 8192 B = 99328 B
    const int smem_bytes = (6*MSIZE + 2048 + 2048) * (int)sizeof(float);
    cudaFuncSetAttribute(wave_kernel, cudaFuncAttributeMaxDynamicSharedMemorySize, smem_bytes);

    zero_flag_kernel<<<2, 256>>>();
    precompute_kernel<<<NV + 6, GG>>>(emb, wih0, bih0, wh2e, bh2e,
                                      whh0, wih1, whh1, wih2, whh2);
    wave_kernel<<<RS, 128, smem_bytes>>>(x, bhh0, bih1, bhh1, bih2, bhh2);
    proj_kernel<<<NTOK/64, 256>>>(wout, bout, pred);
}